// round 8
// baseline (speedup 1.0000x reference)
#include <cuda_runtime.h>

#define NPIX   2304
#define CCH    256
#define NHEADS 8
#define DH     32
#define NBH    16
#define TBL    9025          // (2*48-1)^2
#define QSCALE 0.17677669529663687f

// ---------------- scratch (device globals; no runtime allocation) ----------
__device__ float g_t[2 * NPIX * CCH];        // GDN output, channels-last
__device__ float g_q[NBH * NPIX * DH];       // pre-scaled
__device__ float g_k[NBH * NPIX * DH];
__device__ float g_v[NBH * NPIX * DH];
__device__ float g_res[2 * NPIX * CCH];      // attention out, scrambled rows
__device__ float g_biasT[NHEADS * TBL];      // per-head contiguous bias table

// ---------------- bias table transpose: [9025,8] -> [8][9025] --------------
__global__ void bias_kernel(const float* __restrict__ table) {
    int i = blockIdx.x * 256 + threadIdx.x;
    if (i < NHEADS * TBL) {
        int idx = i >> 3, h = i & 7;
        g_biasT[h * TBL + idx] = table[i];
    }
}

#define GEMM_INNER()                                                              \
    _Pragma("unroll")                                                             \
    for (int kk = 0; kk < 16; ++kk) {                                             \
        float a0 = As[ty4 + 0][kk], a1 = As[ty4 + 1][kk];                         \
        float a2 = As[ty4 + 2][kk], a3 = As[ty4 + 3][kk];                         \
        float b0 = Bs[tx4 + 0][kk], b1 = Bs[tx4 + 1][kk];                         \
        float b2 = Bs[tx4 + 2][kk], b3 = Bs[tx4 + 3][kk];                         \
        acc[0][0] += a0 * b0; acc[0][1] += a0 * b1; acc[0][2] += a0 * b2; acc[0][3] += a0 * b3; \
        acc[1][0] += a1 * b0; acc[1][1] += a1 * b1; acc[1][2] += a1 * b2; acc[1][3] += a1 * b3; \
        acc[2][0] += a2 * b0; acc[2][1] += a2 * b1; acc[2][2] += a2 * b2; acc[2][3] += a2 * b3; \
        acc[3][0] += a3 * b0; acc[3][1] += a3 * b1; acc[3][2] += a3 * b2; acc[3][3] += a3 * b3; \
    }

// ---------------- GDN: norm = gamma @ x^2, t = x * rsqrt(beta + norm) ------
__global__ __launch_bounds__(256) void gdn_kernel(const float* __restrict__ x,
                                                  const float* __restrict__ gamma,
                                                  const float* __restrict__ beta) {
    __shared__ float As[64][17];
    __shared__ float Bs[64][17];
    int tid = threadIdx.x;
    int tx4 = (tid & 15) * 4, ty4 = (tid >> 4) * 4;
    int p0 = blockIdx.y * 64;       // pixel rows (4608 total, tile inside one b)
    int d0 = blockIdx.x * 64;       // output channel cols
    int b  = p0 / NPIX;
    int s0 = p0 - b * NPIX;
    const float* xb = x + b * CCH * NPIX;
    float acc[4][4] = {};
    int rrA = tid & 63, kkA = tid >> 6;     // A load: rr fast (coalesced on s)
    int kkB = tid & 15, jjB = tid >> 4;     // B load: kk fast (coalesced)
    for (int k0 = 0; k0 < CCH; k0 += 16) {
#pragma unroll
        for (int qq = 0; qq < 4; ++qq) {
            float v = xb[(k0 + kkA + 4 * qq) * NPIX + s0 + rrA];
            As[rrA][kkA + 4 * qq] = v * v;
        }
#pragma unroll
        for (int qq = 0; qq < 4; ++qq)
            Bs[jjB + 16 * qq][kkB] = gamma[(d0 + jjB + 16 * qq) * CCH + k0 + kkB];
        __syncthreads();
        GEMM_INNER();
        __syncthreads();
    }
#pragma unroll
    for (int i = 0; i < 4; ++i) {
        int s = s0 + ty4 + i;
        int p = p0 + ty4 + i;
#pragma unroll
        for (int j = 0; j < 4; ++j) {
            int d = d0 + tx4 + j;
            float xv = xb[d * NPIX + s];
            g_t[p * CCH + d] = xv * rsqrtf(beta[d] + acc[i][j]);
        }
    }
}

// ---------------- QKV projection: t @ w_qkv^T, scatter to q/k/v ------------
__global__ __launch_bounds__(256) void qkv_kernel(const float* __restrict__ w) {
    __shared__ float As[64][17];
    __shared__ float Bs[64][17];
    int tid = threadIdx.x;
    int tx4 = (tid & 15) * 4, ty4 = (tid >> 4) * 4;
    int p0 = blockIdx.y * 64;
    int j0 = blockIdx.x * 64;       // output col tile within [0,768)
    int b  = p0 / NPIX;
    int n0 = p0 - b * NPIX;
    float acc[4][4] = {};
    int kkA = tid & 15, rrA = tid >> 4;
    for (int k0 = 0; k0 < CCH; k0 += 16) {
#pragma unroll
        for (int qq = 0; qq < 4; ++qq)
            As[rrA + 16 * qq][kkA] = g_t[(p0 + rrA + 16 * qq) * CCH + k0 + kkA];
#pragma unroll
        for (int qq = 0; qq < 4; ++qq)
            Bs[rrA + 16 * qq][kkA] = w[(j0 + rrA + 16 * qq) * CCH + k0 + kkA];
        __syncthreads();
        GEMM_INNER();
        __syncthreads();
    }
    int sel = j0 >> 8;  // tile lies entirely in one of q/k/v (64 | 256)
    float* dst = (sel == 0) ? g_q : ((sel == 1) ? g_k : g_v);
    float scl  = (sel == 0) ? QSCALE : 1.0f;
#pragma unroll
    for (int i = 0; i < 4; ++i) {
        int n = n0 + ty4 + i;
#pragma unroll
        for (int j = 0; j < 4; ++j) {
            int jj = j0 + tx4 + j;
            int e = jj & 255;
            int h = e >> 5, dd = e & 31;
            dst[((b * NHEADS + h) * NPIX + n) * DH + dd] = acc[i][j] * scl;
        }
    }
}

// ---------------- flash attention with SMEM-resident rel-pos bias ----------
#define ATTN_SMEM_FLOATS (64 * 36 + 32 * 68 + 64 * 36 + 64 * 65 + TBL + 192)
#define ATTN_SMEM_BYTES  (ATTN_SMEM_FLOATS * 4)

__global__ __launch_bounds__(256, 2) void attn_kernel() {
    extern __shared__ float sm[];
    float* sQ  = sm;                 // [64][36] row-major (q rows)
    float* sKT = sQ + 64 * 36;       // [32][68] d-major (conflict-free key vecs)
    float* sV  = sKT + 32 * 68;      // [64][36]
    float* sS  = sV + 64 * 36;       // [64][65] scores / P
    float* sB  = sS + 64 * 65;       // [9025] per-head bias table
    float* sM  = sB + TBL;           // [64] running max
    float* sL  = sM + 64;            // [64] running sum
    float* sF  = sL + 64;            // [64] rescale factor

    int tid = threadIdx.x;
    int tx = tid & 15, ty = tid >> 4;
    int r0 = ty * 4, c0 = tx * 4, d0 = tx * 2;
    int qt = blockIdx.x, bh = blockIdx.y;
    int b = bh >> 3, h = bh & 7;
    int q0 = qt * 64;
    const float* qg = g_q + bh * NPIX * DH;
    const float* kg = g_k + bh * NPIX * DH;
    const float* vg = g_v + bh * NPIX * DH;

    {   // load Q tile (q already scaled)
        const float4* src = (const float4*)(qg + q0 * DH);
#pragma unroll
        for (int it = 0; it < 2; ++it) {
            int l = tid + it * 256;
            float4 vv = src[l];
            int row = l >> 3, dc = (l & 7) << 2;
            *(float4*)&sQ[row * 36 + dc] = vv;
        }
    }
    for (int i = tid; i < TBL; i += 256) sB[i] = g_biasT[h * TBL + i];
    if (tid < 64) { sM[tid] = -1e30f; sL[tid] = 0.f; }

    int qr[4], qc[4];
#pragma unroll
    for (int i = 0; i < 4; ++i) {
        int n = q0 + r0 + i;
        qr[i] = n / 48; qc[i] = n - 48 * qr[i];
    }
    float O0[4] = {0, 0, 0, 0}, O1[4] = {0, 0, 0, 0};
    __syncthreads();

    for (int kt = 0; kt < 36; ++kt) {
        int k0 = kt * 64;
        {   // load K (transpose into d-major) and V
            const float4* ks = (const float4*)(kg + k0 * DH);
            const float4* vs = (const float4*)(vg + k0 * DH);
#pragma unroll
            for (int it = 0; it < 2; ++it) {
                int l = tid + it * 256;
                int row = l >> 3, dc = (l & 7) << 2;
                float4 kv = ks[l];
                sKT[(dc + 0) * 68 + row] = kv.x;
                sKT[(dc + 1) * 68 + row] = kv.y;
                sKT[(dc + 2) * 68 + row] = kv.z;
                sKT[(dc + 3) * 68 + row] = kv.w;
                *(float4*)&sV[row * 36 + dc] = vs[l];
            }
        }
        __syncthreads();

        // S = Q K^T (per-thread 4x4 micro-tile)
        float acc[4][4] = {};
#pragma unroll
        for (int d4 = 0; d4 < 32; d4 += 4) {
            float4 q0v = *(const float4*)&sQ[(r0 + 0) * 36 + d4];
            float4 q1v = *(const float4*)&sQ[(r0 + 1) * 36 + d4];
            float4 q2v = *(const float4*)&sQ[(r0 + 2) * 36 + d4];
            float4 q3v = *(const float4*)&sQ[(r0 + 3) * 36 + d4];
#define QK_STEP(dd, C) {                                                          \
            float4 kc = *(const float4*)&sKT[(d4 + dd) * 68 + c0];                \
            acc[0][0] += q0v.C * kc.x; acc[0][1] += q0v.C * kc.y;                 \
            acc[0][2] += q0v.C * kc.z; acc[0][3] += q0v.C * kc.w;                 \
            acc[1][0] += q1v.C * kc.x; acc[1][1] += q1v.C * kc.y;                 \
            acc[1][2] += q1v.C * kc.z; acc[1][3] += q1v.C * kc.w;                 \
            acc[2][0] += q2v.C * kc.x; acc[2][1] += q2v.C * kc.y;                 \
            acc[2][2] += q2v.C * kc.z; acc[2][3] += q2v.C * kc.w;                 \
            acc[3][0] += q3v.C * kc.x; acc[3][1] += q3v.C * kc.y;                 \
            acc[3][2] += q3v.C * kc.z; acc[3][3] += q3v.C * kc.w; }
            QK_STEP(0, x) QK_STEP(1, y) QK_STEP(2, z) QK_STEP(3, w)
#undef QK_STEP
        }
        // add rel-pos bias (SMEM gather) and stage scores
#pragma unroll
        for (int j = 0; j < 4; ++j) {
            int m = k0 + c0 + j;
            int krr = m / 48, kcc = m - 48 * krr;
#pragma unroll
            for (int i = 0; i < 4; ++i) {
                float bv = sB[(qr[i] - krr + 47) * 95 + (qc[i] - kcc + 47)];
                sS[(r0 + i) * 65 + c0 + j] = acc[i][j] + bv;
            }
        }
        __syncthreads();

        {   // online softmax row phase: 4 threads per row
            int row = tid >> 2, g = tid & 3;
            float mt = -1e30f;
#pragma unroll
            for (int u = 0; u < 16; ++u) mt = fmaxf(mt, sS[row * 65 + g + 4 * u]);
            mt = fmaxf(mt, __shfl_xor_sync(0xffffffffu, mt, 1));
            mt = fmaxf(mt, __shfl_xor_sync(0xffffffffu, mt, 2));
            float mold = sM[row];
            float mnew = fmaxf(mold, mt);
            float psum = 0.f;
#pragma unroll
            for (int u = 0; u < 16; ++u) {
                int c = g + 4 * u;
                float p = __expf(sS[row * 65 + c] - mnew);
                sS[row * 65 + c] = p;
                psum += p;
            }
            psum += __shfl_xor_sync(0xffffffffu, psum, 1);
            psum += __shfl_xor_sync(0xffffffffu, psum, 2);
            if (g == 0) {
                float fac = __expf(mold - mnew);
                sF[row] = fac;
                sM[row] = mnew;
                sL[row] = sL[row] * fac + psum;
            }
        }
        __syncthreads();

        // rescale running O, then O += P V
#pragma unroll
        for (int i = 0; i < 4; ++i) {
            float f = sF[r0 + i];
            O0[i] *= f; O1[i] *= f;
        }
#pragma unroll 4
        for (int kk = 0; kk < 64; ++kk) {
            float2 vv = *(const float2*)&sV[kk * 36 + d0];
#pragma unroll
            for (int i = 0; i < 4; ++i) {
                float p = sS[(r0 + i) * 65 + kk];
                O0[i] += p * vv.x;
                O1[i] += p * vv.y;
            }
        }
        __syncthreads();
    }

    // finalize + scrambled store (reference reshape quirk: n'=h*288+n/8,
    // c'=(n%8)*32+dd), so the output projection is a plain row-major GEMM.
#pragma unroll
    for (int i = 0; i < 4; ++i) {
        int n = q0 + r0 + i;
        float linv = 1.0f / sL[r0 + i];
        int np = h * 288 + (n >> 3);
        int cp = ((n & 7) << 5) + d0;
        float* dst = g_res + (b * NPIX + np) * CCH + cp;
        dst[0] = O0[i] * linv;
        dst[1] = O1[i] * linv;
    }
}

// ---------------- output projection + NCHW store ---------------------------
__global__ __launch_bounds__(256) void out_kernel(const float* __restrict__ w,
                                                  const float* __restrict__ bout,
                                                  float* __restrict__ out) {
    __shared__ float As[64][17];
    __shared__ float Bs[64][17];
    int tid = threadIdx.x;
    int tx4 = (tid & 15) * 4, ty4 = (tid >> 4) * 4;
    int p0 = blockIdx.y * 64;
    int c0b = blockIdx.x * 64;
    int b  = p0 / NPIX;
    int n0 = p0 - b * NPIX;
    float acc[4][4] = {};
    int kkA = tid & 15, rrA = tid >> 4;
    for (int k0 = 0; k0 < CCH; k0 += 16) {
#pragma unroll
        for (int qq = 0; qq < 4; ++qq)
            As[rrA + 16 * qq][kkA] = g_res[(p0 + rrA + 16 * qq) * CCH + k0 + kkA];
#pragma unroll
        for (int qq = 0; qq < 4; ++qq)
            Bs[rrA + 16 * qq][kkA] = w[(c0b + rrA + 16 * qq) * CCH + k0 + kkA];
        __syncthreads();
        GEMM_INNER();
        __syncthreads();
    }
#pragma unroll
    for (int i = 0; i < 4; ++i) {
        int n = n0 + ty4 + i;
#pragma unroll
        for (int j = 0; j < 4; ++j) {
            int c = c0b + tx4 + j;
            out[(b * CCH + c) * NPIX + n] = acc[i][j] + bout[c];
        }
    }
}

// ---------------- launch ---------------------------------------------------
extern "C" void kernel_launch(void* const* d_in, const int* in_sizes, int n_in,
                              void* d_out, int out_size) {
    const float* x     = (const float*)d_in[0];
    const float* beta  = (const float*)d_in[1];
    const float* gamma = (const float*)d_in[2];
    const float* wqkv  = (const float*)d_in[3];
    const float* wout  = (const float*)d_in[4];
    const float* bout  = (const float*)d_in[5];
    const float* table = (const float*)d_in[6];
    float* out = (float*)d_out;
    (void)in_sizes; (void)n_in; (void)out_size;

    cudaFuncSetAttribute(attn_kernel, cudaFuncAttributeMaxDynamicSharedMemorySize,
                         ATTN_SMEM_BYTES);

    bias_kernel<<<(NHEADS * TBL + 255) / 256, 256>>>(table);
    gdn_kernel<<<dim3(4, 72), 256>>>(x, gamma, beta);
    qkv_kernel<<<dim3(12, 72), 256>>>(wqkv);
    attn_kernel<<<dim3(36, 16), 256, ATTN_SMEM_BYTES>>>();
    out_kernel<<<dim3(4, 72), 256>>>(wout, bout, out);
}

// round 16
// speedup vs baseline: 1.2912x; 1.2912x over previous
#include <cuda_runtime.h>

#define NPIX   2304
#define CCH    256
#define NHEADS 8
#define DH     32
#define NBH    16
#define TBL    9025          // (2*48-1)^2
#define QSCALE 0.17677669529663687f

// ---------------- scratch (device globals; no runtime allocation) ----------
__device__ float g_t[2 * NPIX * CCH];        // GDN output, channels-last
__device__ float g_q[NBH * NPIX * DH];       // pre-scaled
__device__ float g_k[NBH * NPIX * DH];
__device__ float g_v[NBH * NPIX * DH];
__device__ float g_res[2 * NPIX * CCH];      // attention out, scrambled rows
__device__ float g_biasT[NHEADS * TBL];      // per-head contiguous bias table

// ---------------- bias table transpose: [9025,8] -> [8][9025] --------------
__global__ void bias_kernel(const float* __restrict__ table) {
    int i = blockIdx.x * 256 + threadIdx.x;
    if (i < NHEADS * TBL) {
        int idx = i >> 3, h = i & 7;
        g_biasT[h * TBL + idx] = table[i];
    }
}

#define GEMM_INNER()                                                              \
    _Pragma("unroll")                                                             \
    for (int kk = 0; kk < 16; ++kk) {                                             \
        float a0 = As[ty4 + 0][kk], a1 = As[ty4 + 1][kk];                         \
        float a2 = As[ty4 + 2][kk], a3 = As[ty4 + 3][kk];                         \
        float b0 = Bs[tx4 + 0][kk], b1 = Bs[tx4 + 1][kk];                         \
        float b2 = Bs[tx4 + 2][kk], b3 = Bs[tx4 + 3][kk];                         \
        acc[0][0] += a0 * b0; acc[0][1] += a0 * b1; acc[0][2] += a0 * b2; acc[0][3] += a0 * b3; \
        acc[1][0] += a1 * b0; acc[1][1] += a1 * b1; acc[1][2] += a1 * b2; acc[1][3] += a1 * b3; \
        acc[2][0] += a2 * b0; acc[2][1] += a2 * b1; acc[2][2] += a2 * b2; acc[2][3] += a2 * b3; \
        acc[3][0] += a3 * b0; acc[3][1] += a3 * b1; acc[3][2] += a3 * b2; acc[3][3] += a3 * b3; \
    }

// ---------------- GDN: norm = gamma @ x^2, t = x * rsqrt(beta + norm) ------
__global__ __launch_bounds__(256) void gdn_kernel(const float* __restrict__ x,
                                                  const float* __restrict__ gamma,
                                                  const float* __restrict__ beta) {
    __shared__ float As[64][17];
    __shared__ float Bs[64][17];
    int tid = threadIdx.x;
    int tx4 = (tid & 15) * 4, ty4 = (tid >> 4) * 4;
    int p0 = blockIdx.y * 64;       // pixel rows (4608 total, tile inside one b)
    int d0 = blockIdx.x * 64;       // output channel cols
    int b  = p0 / NPIX;
    int s0 = p0 - b * NPIX;
    const float* xb = x + b * CCH * NPIX;
    float acc[4][4] = {};
    int rrA = tid & 63, kkA = tid >> 6;     // A load: rr fast (coalesced on s)
    int kkB = tid & 15, jjB = tid >> 4;     // B load: kk fast (coalesced)
    for (int k0 = 0; k0 < CCH; k0 += 16) {
#pragma unroll
        for (int qq = 0; qq < 4; ++qq) {
            float v = xb[(k0 + kkA + 4 * qq) * NPIX + s0 + rrA];
            As[rrA][kkA + 4 * qq] = v * v;
        }
#pragma unroll
        for (int qq = 0; qq < 4; ++qq)
            Bs[jjB + 16 * qq][kkB] = gamma[(d0 + jjB + 16 * qq) * CCH + k0 + kkB];
        __syncthreads();
        GEMM_INNER();
        __syncthreads();
    }
#pragma unroll
    for (int i = 0; i < 4; ++i) {
        int s = s0 + ty4 + i;
        int p = p0 + ty4 + i;
#pragma unroll
        for (int j = 0; j < 4; ++j) {
            int d = d0 + tx4 + j;
            float xv = xb[d * NPIX + s];
            g_t[p * CCH + d] = xv * rsqrtf(beta[d] + acc[i][j]);
        }
    }
}

// ---------------- QKV projection: t @ w_qkv^T, scatter to q/k/v ------------
__global__ __launch_bounds__(256) void qkv_kernel(const float* __restrict__ w) {
    __shared__ float As[64][17];
    __shared__ float Bs[64][17];
    int tid = threadIdx.x;
    int tx4 = (tid & 15) * 4, ty4 = (tid >> 4) * 4;
    int p0 = blockIdx.y * 64;
    int j0 = blockIdx.x * 64;       // output col tile within [0,768)
    int b  = p0 / NPIX;
    int n0 = p0 - b * NPIX;
    float acc[4][4] = {};
    int kkA = tid & 15, rrA = tid >> 4;
    for (int k0 = 0; k0 < CCH; k0 += 16) {
#pragma unroll
        for (int qq = 0; qq < 4; ++qq)
            As[rrA + 16 * qq][kkA] = g_t[(p0 + rrA + 16 * qq) * CCH + k0 + kkA];
#pragma unroll
        for (int qq = 0; qq < 4; ++qq)
            Bs[rrA + 16 * qq][kkA] = w[(j0 + rrA + 16 * qq) * CCH + k0 + kkA];
        __syncthreads();
        GEMM_INNER();
        __syncthreads();
    }
    int sel = j0 >> 8;  // tile lies entirely in one of q/k/v (64 | 256)
    float* dst = (sel == 0) ? g_q : ((sel == 1) ? g_k : g_v);
    float scl  = (sel == 0) ? QSCALE : 1.0f;
#pragma unroll
    for (int i = 0; i < 4; ++i) {
        int n = n0 + ty4 + i;
#pragma unroll
        for (int j = 0; j < 4; ++j) {
            int jj = j0 + tx4 + j;
            int e = jj & 255;
            int h = e >> 5, dd = e & 31;
            dst[((b * NHEADS + h) * NPIX + n) * DH + dd] = acc[i][j] * scl;
        }
    }
}

// ---------------- flash attention with SMEM-resident rel-pos bias ----------
// sS row stride 68 (16B aligned), register softmax, float4 PV
#define ATTN_SMEM_FLOATS (64 * 36 + 32 * 68 + 64 * 36 + 64 * 68 + TBL + 128)
#define ATTN_SMEM_BYTES  (ATTN_SMEM_FLOATS * 4)

__global__ __launch_bounds__(256, 2) void attn_kernel() {
    extern __shared__ float sm[];
    float* sQ  = sm;                 // [64][36] row-major (q rows)
    float* sKT = sQ + 64 * 36;       // [32][68] d-major (conflict-free key vecs)
    float* sV  = sKT + 32 * 68;      // [64][36]
    float* sS  = sV + 64 * 36;       // [64][68] P tile (float4-aligned rows)
    float* sB  = sS + 64 * 68;       // [9025] per-head bias table
    float* sM  = sB + TBL;           // [64] running max
    float* sL  = sM + 64;            // [64] running sum

    int tid = threadIdx.x;
    int tx = tid & 15, ty = tid >> 4;
    int r0 = ty * 4, c0 = tx * 4, d0 = tx * 2;
    int qt = blockIdx.x, bh = blockIdx.y;
    int b = bh >> 3, h = bh & 7;
    int q0 = qt * 64;
    const float* qg = g_q + bh * NPIX * DH;
    const float* kg = g_k + bh * NPIX * DH;
    const float* vg = g_v + bh * NPIX * DH;

    {   // load Q tile (q already scaled)
        const float4* src = (const float4*)(qg + q0 * DH);
#pragma unroll
        for (int it = 0; it < 2; ++it) {
            int l = tid + it * 256;
            float4 vv = src[l];
            int row = l >> 3, dc = (l & 7) << 2;
            *(float4*)&sQ[row * 36 + dc] = vv;
        }
    }
    for (int i = tid; i < TBL; i += 256) sB[i] = g_biasT[h * TBL + i];
    if (tid < 64) { sM[tid] = -1e30f; sL[tid] = 0.f; }

    int qr[4], qc[4];
#pragma unroll
    for (int i = 0; i < 4; ++i) {
        int n = q0 + r0 + i;
        qr[i] = n / 48; qc[i] = n - 48 * qr[i];
    }
    float O0[4] = {0, 0, 0, 0}, O1[4] = {0, 0, 0, 0};
    __syncthreads();

    for (int kt = 0; kt < 36; ++kt) {
        int k0 = kt * 64;
        {   // load K (transpose into d-major) and V
            const float4* ks = (const float4*)(kg + k0 * DH);
            const float4* vs = (const float4*)(vg + k0 * DH);
#pragma unroll
            for (int it = 0; it < 2; ++it) {
                int l = tid + it * 256;
                int row = l >> 3, dc = (l & 7) << 2;
                float4 kv = ks[l];
                sKT[(dc + 0) * 68 + row] = kv.x;
                sKT[(dc + 1) * 68 + row] = kv.y;
                sKT[(dc + 2) * 68 + row] = kv.z;
                sKT[(dc + 3) * 68 + row] = kv.w;
                *(float4*)&sV[row * 36 + dc] = vs[l];
            }
        }
        __syncthreads();

        // S = Q K^T (per-thread 4x4 micro-tile)
        float acc[4][4] = {};
#pragma unroll
        for (int d4 = 0; d4 < 32; d4 += 4) {
            float4 q0v = *(const float4*)&sQ[(r0 + 0) * 36 + d4];
            float4 q1v = *(const float4*)&sQ[(r0 + 1) * 36 + d4];
            float4 q2v = *(const float4*)&sQ[(r0 + 2) * 36 + d4];
            float4 q3v = *(const float4*)&sQ[(r0 + 3) * 36 + d4];
#define QK_STEP(dd, C) {                                                          \
            float4 kc = *(const float4*)&sKT[(d4 + dd) * 68 + c0];                \
            acc[0][0] += q0v.C * kc.x; acc[0][1] += q0v.C * kc.y;                 \
            acc[0][2] += q0v.C * kc.z; acc[0][3] += q0v.C * kc.w;                 \
            acc[1][0] += q1v.C * kc.x; acc[1][1] += q1v.C * kc.y;                 \
            acc[1][2] += q1v.C * kc.z; acc[1][3] += q1v.C * kc.w;                 \
            acc[2][0] += q2v.C * kc.x; acc[2][1] += q2v.C * kc.y;                 \
            acc[2][2] += q2v.C * kc.z; acc[2][3] += q2v.C * kc.w;                 \
            acc[3][0] += q3v.C * kc.x; acc[3][1] += q3v.C * kc.y;                 \
            acc[3][2] += q3v.C * kc.z; acc[3][3] += q3v.C * kc.w; }
            QK_STEP(0, x) QK_STEP(1, y) QK_STEP(2, z) QK_STEP(3, w)
#undef QK_STEP
        }

        // bias add (SMEM gather) into registers
#pragma unroll
        for (int j = 0; j < 4; ++j) {
            int m = k0 + c0 + j;
            int krr = m / 48, kcc = m - 48 * krr;
#pragma unroll
            for (int i = 0; i < 4; ++i)
                acc[i][j] += sB[(qr[i] - krr + 47) * 95 + (qc[i] - kcc + 47)];
        }

        // register-resident online softmax; rows are warp-exclusive
        // (row r0+i owned by 16 lanes differing in lane bits 0..3 = tx)
#pragma unroll
        for (int i = 0; i < 4; ++i) {
            float m = fmaxf(fmaxf(acc[i][0], acc[i][1]), fmaxf(acc[i][2], acc[i][3]));
            m = fmaxf(m, __shfl_xor_sync(0xffffffffu, m, 1));
            m = fmaxf(m, __shfl_xor_sync(0xffffffffu, m, 2));
            m = fmaxf(m, __shfl_xor_sync(0xffffffffu, m, 4));
            m = fmaxf(m, __shfl_xor_sync(0xffffffffu, m, 8));
            float mold = sM[r0 + i];
            float mnew = fmaxf(mold, m);
            float fac  = __expf(mold - mnew);
            float s = 0.f;
#pragma unroll
            for (int j = 0; j < 4; ++j) {
                float p = __expf(acc[i][j] - mnew);
                acc[i][j] = p;
                s += p;
            }
            s += __shfl_xor_sync(0xffffffffu, s, 1);
            s += __shfl_xor_sync(0xffffffffu, s, 2);
            s += __shfl_xor_sync(0xffffffffu, s, 4);
            s += __shfl_xor_sync(0xffffffffu, s, 8);
            if (tx == 0) {
                sM[r0 + i] = mnew;
                sL[r0 + i] = sL[r0 + i] * fac + s;
            }
            O0[i] *= fac; O1[i] *= fac;
            *(float4*)&sS[(r0 + i) * 68 + c0] =
                make_float4(acc[i][0], acc[i][1], acc[i][2], acc[i][3]);
        }
        __syncthreads();

        // O += P V  (float4 P broadcasts, float2 V rows)
#pragma unroll 2
        for (int kk4 = 0; kk4 < 64; kk4 += 4) {
            float p0a[4], p1a[4], p2a[4], p3a[4];
            *(float4*)p0a = *(const float4*)&sS[(r0 + 0) * 68 + kk4];
            *(float4*)p1a = *(const float4*)&sS[(r0 + 1) * 68 + kk4];
            *(float4*)p2a = *(const float4*)&sS[(r0 + 2) * 68 + kk4];
            *(float4*)p3a = *(const float4*)&sS[(r0 + 3) * 68 + kk4];
#pragma unroll
            for (int t = 0; t < 4; ++t) {
                float2 vv = *(const float2*)&sV[(kk4 + t) * 36 + d0];
                O0[0] += p0a[t] * vv.x; O1[0] += p0a[t] * vv.y;
                O0[1] += p1a[t] * vv.x; O1[1] += p1a[t] * vv.y;
                O0[2] += p2a[t] * vv.x; O1[2] += p2a[t] * vv.y;
                O0[3] += p3a[t] * vv.x; O1[3] += p3a[t] * vv.y;
            }
        }
        __syncthreads();
    }

    // finalize + scrambled store (reference reshape quirk: n'=h*288+n/8,
    // c'=(n%8)*32+dd), so the output projection is a plain row-major GEMM.
#pragma unroll
    for (int i = 0; i < 4; ++i) {
        int n = q0 + r0 + i;
        float linv = 1.0f / sL[r0 + i];
        int np = h * 288 + (n >> 3);
        int cp = ((n & 7) << 5) + d0;
        float* dst = g_res + (b * NPIX + np) * CCH + cp;
        dst[0] = O0[i] * linv;
        dst[1] = O1[i] * linv;
    }
}

// ---------------- output projection + NCHW store ---------------------------
__global__ __launch_bounds__(256) void out_kernel(const float* __restrict__ w,
                                                  const float* __restrict__ bout,
                                                  float* __restrict__ out) {
    __shared__ float As[64][17];
    __shared__ float Bs[64][17];
    int tid = threadIdx.x;
    int tx4 = (tid & 15) * 4, ty4 = (tid >> 4) * 4;
    int p0 = blockIdx.y * 64;
    int c0b = blockIdx.x * 64;
    int b  = p0 / NPIX;
    int n0 = p0 - b * NPIX;
    float acc[4][4] = {};
    int kkA = tid & 15, rrA = tid >> 4;
    for (int k0 = 0; k0 < CCH; k0 += 16) {
#pragma unroll
        for (int qq = 0; qq < 4; ++qq)
            As[rrA + 16 * qq][kkA] = g_res[(p0 + rrA + 16 * qq) * CCH + k0 + kkA];
#pragma unroll
        for (int qq = 0; qq < 4; ++qq)
            Bs[rrA + 16 * qq][kkA] = w[(c0b + rrA + 16 * qq) * CCH + k0 + kkA];
        __syncthreads();
        GEMM_INNER();
        __syncthreads();
    }
#pragma unroll
    for (int i = 0; i < 4; ++i) {
        int n = n0 + ty4 + i;
#pragma unroll
        for (int j = 0; j < 4; ++j) {
            int c = c0b + tx4 + j;
            out[(b * CCH + c) * NPIX + n] = acc[i][j] + bout[c];
        }
    }
}

// ---------------- launch ---------------------------------------------------
extern "C" void kernel_launch(void* const* d_in, const int* in_sizes, int n_in,
                              void* d_out, int out_size) {
    const float* x     = (const float*)d_in[0];
    const float* beta  = (const float*)d_in[1];
    const float* gamma = (const float*)d_in[2];
    const float* wqkv  = (const float*)d_in[3];
    const float* wout  = (const float*)d_in[4];
    const float* bout  = (const float*)d_in[5];
    const float* table = (const float*)d_in[6];
    float* out = (float*)d_out;
    (void)in_sizes; (void)n_in; (void)out_size;

    cudaFuncSetAttribute(attn_kernel, cudaFuncAttributeMaxDynamicSharedMemorySize,
                         ATTN_SMEM_BYTES);

    bias_kernel<<<(NHEADS * TBL + 255) / 256, 256>>>(table);
    gdn_kernel<<<dim3(4, 72), 256>>>(x, gamma, beta);
    qkv_kernel<<<dim3(12, 72), 256>>>(wqkv);
    attn_kernel<<<dim3(36, 16), 256, ATTN_SMEM_BYTES>>>();
    out_kernel<<<dim3(4, 72), 256>>>(wout, bout, out);
}

// round 17
// speedup vs baseline: 1.4278x; 1.1058x over previous
#include <cuda_runtime.h>

#define NPIX   2304
#define CCH    256
#define NHEADS 8
#define DH     32
#define NBH    16
#define TBL    9025          // (2*48-1)^2
#define QSCALE 0.17677669529663687f

// ---------------- scratch (device globals; no runtime allocation) ----------
__device__ float g_t[2 * NPIX * CCH];        // GDN output, channels-last
__device__ float g_q[NBH * NPIX * DH];       // pre-scaled
__device__ float g_k[NBH * NPIX * DH];
__device__ float g_v[NBH * NPIX * DH];
__device__ float g_res[2 * NPIX * CCH];      // attention out, scrambled rows
__device__ float g_biasT[NHEADS * TBL];      // per-head contiguous bias table

// ---------------- packed fp32x2 helpers (sm_103a) --------------------------
#define FMA2(acc, a, b) asm("fma.rn.f32x2 %0, %1, %2, %0;" : "+l"(acc) : "l"(a), "l"(b))
#define MUL2(acc, b)    asm("mul.rn.f32x2 %0, %0, %1;"     : "+l"(acc) : "l"(b))
#define PACK2(o, lo, hi)  asm("mov.b64 %0, {%1, %2};" : "=l"(o) : "f"(lo), "f"(hi))
#define UNPK2(lo, hi, in) asm("mov.b64 {%0, %1}, %2;" : "=f"(lo), "=f"(hi) : "l"(in))

// ---------------- bias table transpose: [9025,8] -> [8][9025] --------------
__global__ void bias_kernel(const float* __restrict__ table) {
    int i = blockIdx.x * 256 + threadIdx.x;
    if (i < NHEADS * TBL) {
        int idx = i >> 3, h = i & 7;
        g_biasT[h * TBL + idx] = table[i];
    }
}

#define GEMM_INNER()                                                              \
    _Pragma("unroll")                                                             \
    for (int kk = 0; kk < 16; ++kk) {                                             \
        float a0 = As[ty4 + 0][kk], a1 = As[ty4 + 1][kk];                         \
        float a2 = As[ty4 + 2][kk], a3 = As[ty4 + 3][kk];                         \
        float b0 = Bs[tx4 + 0][kk], b1 = Bs[tx4 + 1][kk];                         \
        float b2 = Bs[tx4 + 2][kk], b3 = Bs[tx4 + 3][kk];                         \
        acc[0][0] += a0 * b0; acc[0][1] += a0 * b1; acc[0][2] += a0 * b2; acc[0][3] += a0 * b3; \
        acc[1][0] += a1 * b0; acc[1][1] += a1 * b1; acc[1][2] += a1 * b2; acc[1][3] += a1 * b3; \
        acc[2][0] += a2 * b0; acc[2][1] += a2 * b1; acc[2][2] += a2 * b2; acc[2][3] += a2 * b3; \
        acc[3][0] += a3 * b0; acc[3][1] += a3 * b1; acc[3][2] += a3 * b2; acc[3][3] += a3 * b3; \
    }

// ---------------- GDN: norm = gamma @ x^2, t = x * rsqrt(beta + norm) ------
__global__ __launch_bounds__(256) void gdn_kernel(const float* __restrict__ x,
                                                  const float* __restrict__ gamma,
                                                  const float* __restrict__ beta) {
    __shared__ float As[64][17];
    __shared__ float Bs[64][17];
    int tid = threadIdx.x;
    int tx4 = (tid & 15) * 4, ty4 = (tid >> 4) * 4;
    int p0 = blockIdx.y * 64;
    int d0 = blockIdx.x * 64;
    int b  = p0 / NPIX;
    int s0 = p0 - b * NPIX;
    const float* xb = x + b * CCH * NPIX;
    float acc[4][4] = {};
    int rrA = tid & 63, kkA = tid >> 6;
    int kkB = tid & 15, jjB = tid >> 4;
    for (int k0 = 0; k0 < CCH; k0 += 16) {
#pragma unroll
        for (int qq = 0; qq < 4; ++qq) {
            float v = xb[(k0 + kkA + 4 * qq) * NPIX + s0 + rrA];
            As[rrA][kkA + 4 * qq] = v * v;
        }
#pragma unroll
        for (int qq = 0; qq < 4; ++qq)
            Bs[jjB + 16 * qq][kkB] = gamma[(d0 + jjB + 16 * qq) * CCH + k0 + kkB];
        __syncthreads();
        GEMM_INNER();
        __syncthreads();
    }
#pragma unroll
    for (int i = 0; i < 4; ++i) {
        int s = s0 + ty4 + i;
        int p = p0 + ty4 + i;
#pragma unroll
        for (int j = 0; j < 4; ++j) {
            int d = d0 + tx4 + j;
            float xv = xb[d * NPIX + s];
            g_t[p * CCH + d] = xv * rsqrtf(beta[d] + acc[i][j]);
        }
    }
}

// ---------------- QKV projection: t @ w_qkv^T, scatter to q/k/v ------------
__global__ __launch_bounds__(256) void qkv_kernel(const float* __restrict__ w) {
    __shared__ float As[64][17];
    __shared__ float Bs[64][17];
    int tid = threadIdx.x;
    int tx4 = (tid & 15) * 4, ty4 = (tid >> 4) * 4;
    int p0 = blockIdx.y * 64;
    int j0 = blockIdx.x * 64;
    int b  = p0 / NPIX;
    int n0 = p0 - b * NPIX;
    float acc[4][4] = {};
    int kkA = tid & 15, rrA = tid >> 4;
    for (int k0 = 0; k0 < CCH; k0 += 16) {
#pragma unroll
        for (int qq = 0; qq < 4; ++qq)
            As[rrA + 16 * qq][kkA] = g_t[(p0 + rrA + 16 * qq) * CCH + k0 + kkA];
#pragma unroll
        for (int qq = 0; qq < 4; ++qq)
            Bs[rrA + 16 * qq][kkA] = w[(j0 + rrA + 16 * qq) * CCH + k0 + kkA];
        __syncthreads();
        GEMM_INNER();
        __syncthreads();
    }
    int sel = j0 >> 8;
    float* dst = (sel == 0) ? g_q : ((sel == 1) ? g_k : g_v);
    float scl  = (sel == 0) ? QSCALE : 1.0f;
#pragma unroll
    for (int i = 0; i < 4; ++i) {
        int n = n0 + ty4 + i;
#pragma unroll
        for (int j = 0; j < 4; ++j) {
            int jj = j0 + tx4 + j;
            int e = jj & 255;
            int h = e >> 5, dd = e & 31;
            dst[((b * NHEADS + h) * NPIX + n) * DH + dd] = acc[i][j] * scl;
        }
    }
}

// ---------------- flash attention: 128-row q tiles, f32x2, d-major K/V -----
#define SQ_OFF   0                       // [128][36]
#define SKT_OFF  (128 * 36)              // [32][68]  K d-major
#define SVT_OFF  (SKT_OFF + 32 * 68)     // [32][68]  V d-major
#define SS_OFF   (SVT_OFF + 32 * 68)     // [128][68] P tile
#define SB_OFF   (SS_OFF + 128 * 68)     // [51*95] bias window (+pad)
#define SM_OFF   (SB_OFF + 4848)
#define SL_OFF   (SM_OFF + 128)
#define ATTN_FLOATS (SL_OFF + 128)
#define ATTN_SMEM_BYTES (ATTN_FLOATS * 4)

__global__ __launch_bounds__(256, 2) void attn_kernel() {
    extern __shared__ float sm[];
    float* sQ  = sm + SQ_OFF;
    float* sKT = sm + SKT_OFF;
    float* sVT = sm + SVT_OFF;
    float* sS  = sm + SS_OFF;
    float* sB  = sm + SB_OFF;
    float* sM  = sm + SM_OFF;
    float* sL  = sm + SL_OFF;

    int tid = threadIdx.x;
    int tx = tid & 15, ty = tid >> 4;
    int r0 = ty * 8, c0 = tx * 4, dcol = tx;   // PV cols: dcol, dcol+16
    int qt = blockIdx.x, bh = blockIdx.y;
    int b = bh >> 3, h = bh & 7;
    int q0 = qt * 128;
    const float* qg = g_q + bh * NPIX * DH;
    const float* kg = g_k + bh * NPIX * DH;
    const float* vg = g_v + bh * NPIX * DH;

    {   // load Q tile [128][32]
        const float4* src = (const float4*)(qg + q0 * DH);
#pragma unroll
        for (int it = 0; it < 4; ++it) {
            int l = tid + it * 256;
            float4 vv = src[l];
            *(float4*)&sQ[(l >> 3) * 36 + ((l & 7) << 2)] = vv;
        }
    }
    // bias window: rows [qr0 .. qr0+50] of the 95x95 per-head table
    int qr0 = q0 / 48;
    {
        int base = h * TBL + qr0 * 95;
        int cnt  = TBL - qr0 * 95; if (cnt > 4845) cnt = 4845;
        for (int i = tid; i < cnt; i += 256) sB[i] = g_biasT[base + i];
    }
    if (tid < 128) { sM[tid] = -1e30f; sL[tid] = 0.f; }

    int basei[8];
#pragma unroll
    for (int i = 0; i < 8; ++i) {
        int n = q0 + r0 + i;
        int qr = n / 48, qc = n - 48 * qr;
        basei[i] = (qr - qr0 + 47) * 95 + qc + 47;
    }
    unsigned long long Oe[8][2] = {};   // packed (even-kk, odd-kk) partials
    __syncthreads();

    for (int kt = 0; kt < 36; ++kt) {
        int k0 = kt * 64;
        {   // K,V -> d-major smem; row-fast mapping -> conflict-free STS
            const float4* ks = (const float4*)(kg + k0 * DH);
            const float4* vs = (const float4*)(vg + k0 * DH);
#pragma unroll
            for (int it = 0; it < 2; ++it) {
                int l = tid + it * 256;
                int row = l & 63, dc4 = (l >> 6) << 2;
                float4 kv = ks[row * 8 + (l >> 6)];
                sKT[(dc4 + 0) * 68 + row] = kv.x;
                sKT[(dc4 + 1) * 68 + row] = kv.y;
                sKT[(dc4 + 2) * 68 + row] = kv.z;
                sKT[(dc4 + 3) * 68 + row] = kv.w;
                float4 vv = vs[row * 8 + (l >> 6)];
                sVT[(dc4 + 0) * 68 + row] = vv.x;
                sVT[(dc4 + 1) * 68 + row] = vv.y;
                sVT[(dc4 + 2) * 68 + row] = vv.z;
                sVT[(dc4 + 3) * 68 + row] = vv.w;
            }
        }
        __syncthreads();

        // ---- S = Q K^T : 8x4 micro-tile, packed over column pairs ----
        unsigned long long accp[8][2] = {};
        for (int d4 = 0; d4 < 32; d4 += 4) {
            ulonglong2 kcp[4];
#pragma unroll
            for (int dd = 0; dd < 4; ++dd)
                kcp[dd] = *(const ulonglong2*)&sKT[(d4 + dd) * 68 + c0];
#pragma unroll
            for (int half = 0; half < 8; half += 4) {
                float4 qv[4];
#pragma unroll
                for (int i = 0; i < 4; ++i)
                    qv[i] = *(const float4*)&sQ[(r0 + half + i) * 36 + d4];
#pragma unroll
                for (int dd = 0; dd < 4; ++dd) {
#pragma unroll
                    for (int i = 0; i < 4; ++i) {
                        float qs = (dd == 0) ? qv[i].x : (dd == 1) ? qv[i].y
                                 : (dd == 2) ? qv[i].z : qv[i].w;
                        unsigned long long qp; PACK2(qp, qs, qs);
                        FMA2(accp[half + i][0], qp, kcp[dd].x);
                        FMA2(accp[half + i][1], qp, kcp[dd].y);
                    }
                }
            }
        }

        // bias offsets for this kv tile's 4 columns
        int offj[4];
#pragma unroll
        for (int j = 0; j < 4; ++j) {
            int m = k0 + c0 + j;
            int krr = m / 48, kcc = m - 48 * krr;
            offj[j] = krr * 95 + kcc;
        }

        // ---- register online softmax (rows warp-exclusive over tx lanes) ----
#pragma unroll
        for (int i = 0; i < 8; ++i) {
            float a[4];
            UNPK2(a[0], a[1], accp[i][0]);
            UNPK2(a[2], a[3], accp[i][1]);
#pragma unroll
            for (int j = 0; j < 4; ++j) a[j] += sB[basei[i] - offj[j]];
            float mx = fmaxf(fmaxf(a[0], a[1]), fmaxf(a[2], a[3]));
            mx = fmaxf(mx, __shfl_xor_sync(0xffffffffu, mx, 1));
            mx = fmaxf(mx, __shfl_xor_sync(0xffffffffu, mx, 2));
            mx = fmaxf(mx, __shfl_xor_sync(0xffffffffu, mx, 4));
            mx = fmaxf(mx, __shfl_xor_sync(0xffffffffu, mx, 8));
            float mold = sM[r0 + i];
            float mnew = fmaxf(mold, mx);
            float fac  = __expf(mold - mnew);
            float s = 0.f;
#pragma unroll
            for (int j = 0; j < 4; ++j) {
                a[j] = __expf(a[j] - mnew);
                s += a[j];
            }
            s += __shfl_xor_sync(0xffffffffu, s, 1);
            s += __shfl_xor_sync(0xffffffffu, s, 2);
            s += __shfl_xor_sync(0xffffffffu, s, 4);
            s += __shfl_xor_sync(0xffffffffu, s, 8);
            if (tx == 0) {
                sM[r0 + i] = mnew;
                sL[r0 + i] = sL[r0 + i] * fac + s;
            }
            unsigned long long fp; PACK2(fp, fac, fac);
            MUL2(Oe[i][0], fp);
            MUL2(Oe[i][1], fp);
            *(float4*)&sS[(r0 + i) * 68 + c0] = make_float4(a[0], a[1], a[2], a[3]);
        }
        __syncwarp();   // P rows are warp-local; no block sync needed here

        // ---- O += P V : packed even/odd kk pairs, zero packing movs ----
#pragma unroll 4
        for (int kk4 = 0; kk4 < 64; kk4 += 4) {
            ulonglong2 vt0 = *(const ulonglong2*)&sVT[(dcol)      * 68 + kk4];
            ulonglong2 vt1 = *(const ulonglong2*)&sVT[(dcol + 16) * 68 + kk4];
#pragma unroll
            for (int i = 0; i < 8; ++i) {
                ulonglong2 pp = *(const ulonglong2*)&sS[(r0 + i) * 68 + kk4];
                FMA2(Oe[i][0], pp.x, vt0.x);
                FMA2(Oe[i][0], pp.y, vt0.y);
                FMA2(Oe[i][1], pp.x, vt1.x);
                FMA2(Oe[i][1], pp.y, vt1.y);
            }
        }
        __syncthreads();
    }

    // finalize (merge even/odd partials) + scrambled store for out-proj GEMM
#pragma unroll
    for (int i = 0; i < 8; ++i) {
        int n = q0 + r0 + i;
        float linv = 1.0f / sL[r0 + i];
        float e0, o0, e1, o1;
        UNPK2(e0, o0, Oe[i][0]);
        UNPK2(e1, o1, Oe[i][1]);
        int np = h * 288 + (n >> 3);
        int cp = ((n & 7) << 5);
        float* dst = g_res + (b * NPIX + np) * CCH + cp;
        dst[dcol]      = (e0 + o0) * linv;
        dst[dcol + 16] = (e1 + o1) * linv;
    }
}

// ---------------- output projection + NCHW store ---------------------------
__global__ __launch_bounds__(256) void out_kernel(const float* __restrict__ w,
                                                  const float* __restrict__ bout,
                                                  float* __restrict__ out) {
    __shared__ float As[64][17];
    __shared__ float Bs[64][17];
    int tid = threadIdx.x;
    int tx4 = (tid & 15) * 4, ty4 = (tid >> 4) * 4;
    int p0 = blockIdx.y * 64;
    int c0b = blockIdx.x * 64;
    int b  = p0 / NPIX;
    int n0 = p0 - b * NPIX;
    float acc[4][4] = {};
    int kkA = tid & 15, rrA = tid >> 4;
    for (int k0 = 0; k0 < CCH; k0 += 16) {
#pragma unroll
        for (int qq = 0; qq < 4; ++qq)
            As[rrA + 16 * qq][kkA] = g_res[(p0 + rrA + 16 * qq) * CCH + k0 + kkA];
#pragma unroll
        for (int qq = 0; qq < 4; ++qq)
            Bs[rrA + 16 * qq][kkA] = w[(c0b + rrA + 16 * qq) * CCH + k0 + kkA];
        __syncthreads();
        GEMM_INNER();
        __syncthreads();
    }
#pragma unroll
    for (int i = 0; i < 4; ++i) {
        int n = n0 + ty4 + i;
#pragma unroll
        for (int j = 0; j < 4; ++j) {
            int c = c0b + tx4 + j;
            out[(b * CCH + c) * NPIX + n] = acc[i][j] + bout[c];
        }
    }
}

// ---------------- launch ---------------------------------------------------
extern "C" void kernel_launch(void* const* d_in, const int* in_sizes, int n_in,
                              void* d_out, int out_size) {
    const float* x     = (const float*)d_in[0];
    const float* beta  = (const float*)d_in[1];
    const float* gamma = (const float*)d_in[2];
    const float* wqkv  = (const float*)d_in[3];
    const float* wout  = (const float*)d_in[4];
    const float* bout  = (const float*)d_in[5];
    const float* table = (const float*)d_in[6];
    float* out = (float*)d_out;
    (void)in_sizes; (void)n_in; (void)out_size;

    cudaFuncSetAttribute(attn_kernel, cudaFuncAttributeMaxDynamicSharedMemorySize,
                         ATTN_SMEM_BYTES);

    bias_kernel<<<(NHEADS * TBL + 255) / 256, 256>>>(table);
    gdn_kernel<<<dim3(4, 72), 256>>>(x, gamma, beta);
    qkv_kernel<<<dim3(12, 72), 256>>>(wqkv);
    attn_kernel<<<dim3(18, 16), 256, ATTN_SMEM_BYTES>>>();
    out_kernel<<<dim3(4, 72), 256>>>(wout, bout, out);
}